// round 11
// baseline (speedup 1.0000x reference)
#include <cuda_runtime.h>
#include <cuda_fp16.h>
#include <math.h>

// ContractiveMessageBlock — Round 10: 512-thread CTA (TM=256, 4 warps/SMSP),
// single-pass fp16 HMMA, silu-from-fragments, 8-row two-pass dump/epilogue,
// in-epilogue sin-recurrence RBF filter, Wr resident in smem, split0 in global.

#define E_TOT   200000
#define FEAT    128
#define TM      256
#define THREADS 512
#define NBLK    ((E_TOT + TM - 1) / TM)   // 782
#define NB      2000
#define NRBF    20
#define PI_OVER_CUT 0.62831853071795864769f

typedef unsigned long long u64;
typedef unsigned int u32;

// ---------------- f32x2 / misc helpers ----------------
__device__ __forceinline__ u64 fma2(u64 a, u64 b, u64 c) {
    u64 d; asm("fma.rn.f32x2 %0, %1, %2, %3;" : "=l"(d) : "l"(a), "l"(b), "l"(c)); return d;
}
__device__ __forceinline__ u64 mul2(u64 a, u64 b) {
    u64 d; asm("mul.rn.f32x2 %0, %1, %2;" : "=l"(d) : "l"(a), "l"(b)); return d;
}
__device__ __forceinline__ u64 add2(u64 a, u64 b) {
    u64 d; asm("add.rn.f32x2 %0, %1, %2;" : "=l"(d) : "l"(a), "l"(b)); return d;
}
__device__ __forceinline__ u64 dup2(float x) {
    u64 d; asm("mov.b64 %0, {%1, %1};" : "=l"(d) : "f"(x)); return d;
}
__device__ __forceinline__ u64 pk2(float a, float b) {
    u64 d; asm("mov.b64 %0, {%1, %2};" : "=l"(d) : "f"(a), "f"(b)); return d;
}
__device__ __forceinline__ void unpack2(u64 a, float& lo, float& hi) {
    asm("mov.b64 {%0, %1}, %2;" : "=f"(lo), "=f"(hi) : "l"(a));
}
__device__ __forceinline__ void red_add_v4(float* p, float a, float b, float c, float d) {
    asm volatile("red.global.add.v4.f32 [%0], {%1, %2, %3, %4};"
                 :: "l"(p), "f"(a), "f"(b), "f"(c), "f"(d) : "memory");
}
__device__ __forceinline__ u32 smem_u32(const void* p) {
    u32 a; asm("{ .reg .u64 t; cvta.to.shared.u64 t, %1; cvt.u32.u64 %0, t; }"
               : "=r"(a) : "l"(p));
    return a;
}
__device__ __forceinline__ void cpa16(u32 s, const void* g) {
    asm volatile("cp.async.cg.shared.global [%0], [%1], 16;" :: "r"(s), "l"(g));
}
__device__ __forceinline__ void cpa_commit() {
    asm volatile("cp.async.commit_group;" ::: "memory");
}
__device__ __forceinline__ void cpa_wait0() {
    asm volatile("cp.async.wait_group 0;" ::: "memory");
}

// ---------------- mma / ldmatrix ----------------
__device__ __forceinline__ void ldsm4(u32* r, u32 addr) {
    asm volatile("ldmatrix.sync.aligned.m8n8.x4.shared.b16 {%0,%1,%2,%3}, [%4];"
                 : "=r"(r[0]), "=r"(r[1]), "=r"(r[2]), "=r"(r[3]) : "r"(addr));
}
__device__ __forceinline__ void mma16816(float* d, const u32* a, u32 b0, u32 b1) {
    asm volatile(
        "mma.sync.aligned.m16n8k16.row.col.f32.f16.f16.f32 "
        "{%0,%1,%2,%3}, {%4,%5,%6,%7}, {%8,%9}, {%0,%1,%2,%3};"
        : "+f"(d[0]), "+f"(d[1]), "+f"(d[2]), "+f"(d[3])
        : "r"(a[0]), "r"(a[1]), "r"(a[2]), "r"(a[3]), "r"(b0), "r"(b1));
}

// fp16 tile [rows][128 k]: 16B granules, XOR swizzle (rows up to 256).
__device__ __host__ __forceinline__ int toff(int row, int kg) {
    return row * 256 + (((kg ^ (row & 7)) & 15) << 4);
}
// fp32 scratch [128 rows][128 c], 4-word-granule XOR swizzle.
__device__ __forceinline__ int scr_w(int e, int c) {
    return e * 128 + (((((c >> 2)) ^ (e & 7)) & 31) << 2) + (c & 3);
}
__device__ __forceinline__ float silu_f(float x) {
    return x / (1.0f + __expf(-x));
}

// ---------------- global scratch ----------------
__device__ __align__(16) float g_acc_s[NB * FEAT];      // [bin][f]
__device__ __align__(16) float g_acc_v[NB * 3 * FEAT];  // [bin][x][f]
__device__ float g_cnt[NB];
__device__ __align__(16) float g_split0[(size_t)NBLK * TM * FEAT];  // chunk-0 stash
__device__ __align__(16) unsigned char g_W1[32768];          // fp16 tile
__device__ __align__(16) unsigned char g_W2[3 * 32768];      // fp16 tiles

// ---------------- smem offsets (bytes) ----------------
#define OFF_A    0        // 65536  A then H, fp16 [256][128]
#define OFF_W    65536    // 32768  current W tile (fp16)
#define OFF_SCR  98304    // 65536  fp32 D dump [128 rows][128] (warp w rows w*8..w*8+7)
#define OFF_WR   163840   // 30720  Wr fp32 [20][384]
#define OFF_S1   194560   // 1024   sin(theta)/d  per edge
#define OFF_TC   195584   // 1024   2cos(theta)   per edge
#define OFF_ENV  196608   // 1024
#define OFF_UNIT 197632   // 3072   [3][256]
#define OFF_BIN  200704   // 1024 (int)
#define SMEM_BYTES 201728

__global__ void cmb_zero() {
    int i = blockIdx.x * 256 + threadIdx.x;
    if (i < NB * FEAT)     g_acc_s[i] = 0.0f;
    if (i < NB * 3 * FEAT) g_acc_v[i] = 0.0f;
    if (i < NB)            g_cnt[i]   = 0.0f;
}

// W1/W2 -> fp16 tiles in swizzled [n][k] layout (B operand, TN gemm).
__global__ void cmb_prep(const float* __restrict__ W1, const float* __restrict__ W2) {
    int i = blockIdx.x * 256 + threadIdx.x;     // 0..65535
    if (i < 16384) {
        int n = i & 127, k = i >> 7;
        float v = W1[k * 128 + n];
        int off = toff(n, k >> 3) + (k & 7) * 2;
        *(__half*)(g_W1 + off) = __float2half_rn(v);
    } else if (i < 65536) {
        int r = i - 16384;
        int c = r >> 14;
        int t = r & 16383;
        int n = t & 127, k = t >> 7;
        float v = W2[k * 384 + c * 128 + n];
        int off = c * 32768 + toff(n, k >> 3) + (k & 7) * 2;
        *(__half*)(g_W2 + off) = __float2half_rn(v);
    }
}

// Issue cp.async for one 32KB W tile.
__device__ __forceinline__ void copyW_async(u32 dst, const unsigned char* g, int tid) {
    #pragma unroll
    for (int t = 0; t < 4; t++) {
        int i = tid + t * THREADS;
        cpa16(dst + i * 16, g + i * 16);
    }
}

// Single-pass fp16 GEMM: acc += A(warp stripe) * B. 128 HMMA per call.
__device__ __forceinline__ void gemm_tile(u32 aT, u32 bW,
                                          int m0, int lane, float acc[16][4]) {
    const int r  = lane & 7;
    const int hf = (lane >> 3) & 1;
    const int kq = lane >> 4;
    const int arow = m0 + hf * 8 + r;
    const int brow = hf * 8 + r;
    #pragma unroll
    for (int ks = 0; ks < 8; ks++) {
        int kg = ks * 2 + kq;
        u32 a[4];
        ldsm4(a, aT + (u32)toff(arow, kg));
        #pragma unroll
        for (int ng = 0; ng < 8; ng++) {
            u32 b[4];
            ldsm4(b, bW + (u32)toff(ng * 16 + brow, kg));
            mma16816(acc[2 * ng],     a, b[0], b[2]);
            mma16816(acc[2 * ng + 1], a, b[1], b[3]);
        }
    }
}

// Dump one 8-row pass (p=0: acc rows r0; p=1: acc rows r0+8) into warp's SCR stripe.
__device__ __forceinline__ void dump_pass(float* scr, const float acc[16][4],
                                          int warp, int lane, int p) {
    const int row = warp * 8 + (lane >> 2);
    const int cb  = (lane & 3) * 2;
    #pragma unroll
    for (int ng = 0; ng < 8; ng++)
        #pragma unroll
        for (int s = 0; s < 2; s++) {
            int c = ng * 16 + s * 8 + cb;
            const float* a = acc[2 * ng + s];
            *(float2*)&scr[scr_w(row, c)] = make_float2(a[2 * p], a[2 * p + 1]);
        }
}

// Fused epilogue for chunk C, one 8-edge pass.
template <int C>
__device__ __forceinline__ void epi_pass(
    const float* sScr, const float* sWr, const float* sS1, const float* sTC,
    const float* sEnv, const float* sUnit, const int* sBin,
    const float* __restrict__ v_i,
    const float* __restrict__ b2, const float* __restrict__ br,
    long e0, int nvalid, int warp, int lane, int p)
{
    const int j0  = lane * 4;
    const int ebl = warp * 16 + p * 8;
    const int sr  = warp * 8;

    float4 brv = *(const float4*)&br[C * 128 + j0];
    u64 ws0[8], ws1[8];
    float sn[8], sp[8], tc[8];
    #pragma unroll
    for (int e = 0; e < 8; e++) {
        ws0[e] = pk2(brv.x, brv.y);
        ws1[e] = pk2(brv.z, brv.w);
        sn[e]  = sS1[ebl + e];
        sp[e]  = 0.0f;
        tc[e]  = sTC[ebl + e];
    }
    // ws = sum_n rbf_n * Wr[n], rbf via scaled sin recurrence
    #pragma unroll
    for (int n = 0; n < NRBF; n++) {
        float4 w = *(const float4*)&sWr[n * 384 + C * 128 + j0];
        u64 wa = pk2(w.x, w.y), wb = pk2(w.z, w.w);
        #pragma unroll
        for (int e = 0; e < 8; e++) {
            u64 sd = dup2(sn[e]);
            ws0[e] = fma2(sd, wa, ws0[e]);
            ws1[e] = fma2(sd, wb, ws1[e]);
            float nx = fmaf(tc[e], sn[e], -sp[e]);
            sp[e] = sn[e]; sn[e] = nx;
        }
    }

    float4 b2v = *(const float4*)&b2[C * 128 + j0];
    u64 b2a = pk2(b2v.x, b2v.y), b2b = pk2(b2v.z, b2v.w);

    #pragma unroll
    for (int e = 0; e < 8; e++) {
        int ei = ebl + e;
        float4 d = *(const float4*)&sScr[scr_w(sr + e, j0)];
        u64 envd = dup2(sEnv[ei]);
        u64 i01 = mul2(add2(pk2(d.x, d.y), b2a), mul2(ws0[e], envd));
        u64 i23 = mul2(add2(pk2(d.z, d.w), b2b), mul2(ws1[e], envd));
        float i0, i1, i2, i3;
        unpack2(i01, i0, i1); unpack2(i23, i2, i3);

        if (ei < nvalid) {
            if (C == 0) {
                *(float4*)&g_split0[((size_t)e0 + ei) * FEAT + j0] =
                    make_float4(i0, i1, i2, i3);
            } else if (C == 1) {
                int bin = sBin[ei];
                red_add_v4(&g_acc_s[bin * FEAT + j0], i0, i1, i2, i3);
            } else {
                int bin = sBin[ei];
                float4 s0 = *(const float4*)&g_split0[((size_t)e0 + ei) * FEAT + j0];
                const float4* vg =
                    (const float4*)(v_i + (((size_t)e0 + ei) * FEAT + j0) * 3);
                float4 va = vg[0], vb = vg[1], vc2 = vg[2];
                float vf[12] = { va.x, va.y, va.z, va.w,
                                 vb.x, vb.y, vb.z, vb.w,
                                 vc2.x, vc2.y, vc2.z, vc2.w };
                float uu[3] = { sUnit[ei], sUnit[256 + ei], sUnit[512 + ei] };
                #pragma unroll
                for (int x = 0; x < 3; x++)
                    red_add_v4(&g_acc_v[bin * 3 * FEAT + x * FEAT + j0],
                        fmaf(i0, uu[x], s0.x * vf[0 + x]),
                        fmaf(i1, uu[x], s0.y * vf[3 + x]),
                        fmaf(i2, uu[x], s0.z * vf[6 + x]),
                        fmaf(i3, uu[x], s0.w * vf[9 + x]));
            }
        }
    }
}

__global__ void __launch_bounds__(THREADS, 1)
cmb_main(const float* __restrict__ s_i, const float* __restrict__ v_i,
         const float* __restrict__ r_iI, const float* __restrict__ b1,
         const float* __restrict__ b2, const float* __restrict__ Wr_g,
         const float* __restrict__ br, const int* __restrict__ mapping)
{
    extern __shared__ char smem[];
    const u32 sb = smem_u32(smem);
    float* sScr  = (float*)(smem + OFF_SCR);
    float* sWr   = (float*)(smem + OFF_WR);
    float* sS1   = (float*)(smem + OFF_S1);
    float* sTC   = (float*)(smem + OFF_TC);
    float* sEnv  = (float*)(smem + OFF_ENV);
    float* sUnit = (float*)(smem + OFF_UNIT);
    int*   sBin  = (int*)(smem + OFF_BIN);

    const int tid  = threadIdx.x;
    const int lane = tid & 31;
    const int warp = tid >> 5;
    const int m0   = warp * 16;
    const long e0  = (long)blockIdx.x * TM;
    const int nvalid = (int)min((long)TM, (long)E_TOT - e0);

    // ---- prefetch W1 + full Wr (single group) ----
    copyW_async(sb + OFF_W, g_W1, tid);
    #pragma unroll
    for (int t = 0; t < 4; t++) {
        int i = tid + t * THREADS;
        if (i < 1920) cpa16(sb + OFF_WR + i * 16, (const char*)Wr_g + i * 16);
    }
    cpa_commit();

    // ---- A tile: s_i -> fp16 swizzled (256 rows) ----
    for (int i = tid; i < TM * 16; i += THREADS) {
        int row = i >> 4, kg = i & 15;
        float4 va, vb;
        if (row < nvalid) {
            const float4* g = (const float4*)(s_i + ((size_t)(e0 + row)) * FEAT + kg * 8);
            va = g[0]; vb = g[1];
        } else {
            va = make_float4(0.f, 0.f, 0.f, 0.f); vb = va;
        }
        __half2 h0 = __floats2half2_rn(va.x, va.y);
        __half2 h1 = __floats2half2_rn(va.z, va.w);
        __half2 h2 = __floats2half2_rn(vb.x, vb.y);
        __half2 h3 = __floats2half2_rn(vb.z, vb.w);
        int off = toff(row, kg);
        *(uint4*)(smem + OFF_A + off) =
            make_uint4(*(u32*)&h0, *(u32*)&h1, *(u32*)&h2, *(u32*)&h3);
    }
    // ---- per-edge preprocess ----
    if (tid < TM) {
        int e = tid;
        if (e < nvalid) {
            long eg = e0 + e;
            float r0 = r_iI[eg * 3 + 0], r1 = r_iI[eg * 3 + 1], r2 = r_iI[eg * 3 + 2];
            float d = sqrtf(r0 * r0 + r1 * r1 + r2 * r2 + 3e-8f);
            float id = 1.0f / d;
            sUnit[0 * 256 + e] = r0 * id;
            sUnit[1 * 256 + e] = r1 * id;
            sUnit[2 * 256 + e] = r2 * id;
            float theta = PI_OVER_CUT * d;
            float s1, c1;
            sincosf(theta, &s1, &c1);
            sEnv[e] = (d < 5.0f) ? 0.5f * (c1 + 1.0f) : 0.0f;
            sS1[e]  = s1 * id;        // scaled recurrence seed
            sTC[e]  = 2.0f * c1;
            int b = mapping[eg];
            sBin[e] = b;
            atomicAdd(&g_cnt[b], 1.0f);
        } else {
            sUnit[e] = sUnit[256 + e] = sUnit[512 + e] = 0.0f;
            sEnv[e] = 0.0f; sS1[e] = 0.0f; sTC[e] = 0.0f; sBin[e] = 0;
        }
    }
    cpa_wait0();
    __syncthreads();          // A, W1, Wr, preprocess visible

    float acc[16][4];

    // ---- GEMM1 ----
    #pragma unroll
    for (int q = 0; q < 16; q++)
        acc[q][0] = acc[q][1] = acc[q][2] = acc[q][3] = 0.0f;
    gemm_tile(sb + OFF_A, sb + OFF_W, m0, lane, acc);
    __syncthreads();          // all warps done reading W1
    copyW_async(sb + OFF_W, g_W2, tid);          // prefetch chunk0
    cpa_commit();

    // ---- silu directly from fragments -> H fp16 in A tile (warp-local rows) ----
    {
        const int r0 = m0 + (lane >> 2);
        const int cb = (lane & 3) * 2;
        #pragma unroll
        for (int ng = 0; ng < 8; ng++)
            #pragma unroll
            for (int s = 0; s < 2; s++) {
                int c = ng * 16 + s * 8 + cb;
                float2 bb = *(const float2*)&b1[c];
                const float* a = acc[2 * ng + s];
                __half2 hA = __floats2half2_rn(silu_f(a[0] + bb.x),
                                               silu_f(a[1] + bb.y));
                __half2 hB = __floats2half2_rn(silu_f(a[2] + bb.x),
                                               silu_f(a[3] + bb.y));
                int kg = c >> 3, kb = (c & 7) * 2;
                *(__half2*)(smem + OFF_A + toff(r0,     kg) + kb) = hA;
                *(__half2*)(smem + OFF_A + toff(r0 + 8, kg) + kb) = hB;
            }
    }
    cpa_wait0();
    __syncthreads();          // H (all warps, since syncthreads) + W2[0] ready

    // ---- GEMM2 chunk 0 ----
    #pragma unroll
    for (int q = 0; q < 16; q++)
        acc[q][0] = acc[q][1] = acc[q][2] = acc[q][3] = 0.0f;
    gemm_tile(sb + OFF_A, sb + OFF_W, m0, lane, acc);
    __syncthreads();
    copyW_async(sb + OFF_W, g_W2 + 32768, tid);  // prefetch chunk1
    cpa_commit();
    dump_pass(sScr, acc, warp, lane, 0);
    __syncwarp();
    epi_pass<0>(sScr, sWr, sS1, sTC, sEnv, sUnit, sBin, v_i, b2, br,
                e0, nvalid, warp, lane, 0);
    __syncwarp();
    dump_pass(sScr, acc, warp, lane, 1);
    __syncwarp();
    epi_pass<0>(sScr, sWr, sS1, sTC, sEnv, sUnit, sBin, v_i, b2, br,
                e0, nvalid, warp, lane, 1);
    cpa_wait0();
    __syncthreads();

    // ---- GEMM2 chunk 1 ----
    #pragma unroll
    for (int q = 0; q < 16; q++)
        acc[q][0] = acc[q][1] = acc[q][2] = acc[q][3] = 0.0f;
    gemm_tile(sb + OFF_A, sb + OFF_W, m0, lane, acc);
    __syncthreads();
    copyW_async(sb + OFF_W, g_W2 + 65536, tid);  // prefetch chunk2
    cpa_commit();
    dump_pass(sScr, acc, warp, lane, 0);
    __syncwarp();
    epi_pass<1>(sScr, sWr, sS1, sTC, sEnv, sUnit, sBin, v_i, b2, br,
                e0, nvalid, warp, lane, 0);
    __syncwarp();
    dump_pass(sScr, acc, warp, lane, 1);
    __syncwarp();
    epi_pass<1>(sScr, sWr, sS1, sTC, sEnv, sUnit, sBin, v_i, b2, br,
                e0, nvalid, warp, lane, 1);
    cpa_wait0();
    __syncthreads();

    // ---- GEMM2 chunk 2 ----
    #pragma unroll
    for (int q = 0; q < 16; q++)
        acc[q][0] = acc[q][1] = acc[q][2] = acc[q][3] = 0.0f;
    gemm_tile(sb + OFF_A, sb + OFF_W, m0, lane, acc);
    dump_pass(sScr, acc, warp, lane, 0);
    __syncwarp();
    epi_pass<2>(sScr, sWr, sS1, sTC, sEnv, sUnit, sBin, v_i, b2, br,
                e0, nvalid, warp, lane, 0);
    __syncwarp();
    dump_pass(sScr, acc, warp, lane, 1);
    __syncwarp();
    epi_pass<2>(sScr, sWr, sS1, sTC, sEnv, sUnit, sBin, v_i, b2, br,
                e0, nvalid, warp, lane, 1);
}

__global__ void cmb_final(float* __restrict__ out) {
    int bin = blockIdx.x;
    int f   = threadIdx.x;
    float ic = 1.0f / fmaxf(g_cnt[bin], 1.0f);
    out[bin * FEAT + f] = g_acc_s[bin * FEAT + f] * ic;
    #pragma unroll
    for (int x = 0; x < 3; x++)
        out[NB * FEAT + bin * 384 + f * 3 + x] =
            g_acc_v[bin * 3 * FEAT + x * FEAT + f] * ic;
}

extern "C" void kernel_launch(void* const* d_in, const int* in_sizes, int n_in,
                              void* d_out, int out_size)
{
    const float* s_i     = (const float*)d_in[0];
    const float* v_i     = (const float*)d_in[1];
    const float* r_iI    = (const float*)d_in[2];
    const float* W1      = (const float*)d_in[3];
    const float* b1      = (const float*)d_in[4];
    const float* W2      = (const float*)d_in[5];
    const float* b2      = (const float*)d_in[6];
    const float* Wr      = (const float*)d_in[7];
    const float* br      = (const float*)d_in[8];
    const int*   mapping = (const int*)d_in[9];
    float* out = (float*)d_out;
    (void)in_sizes; (void)n_in; (void)out_size;

    cudaFuncSetAttribute((const void*)cmb_main,
                         cudaFuncAttributeMaxDynamicSharedMemorySize, SMEM_BYTES);

    cmb_prep<<<256, 256>>>(W1, W2);
    cmb_zero<<<(NB * 3 * FEAT + 255) / 256, 256>>>();
    cmb_main<<<NBLK, THREADS, SMEM_BYTES>>>(s_i, v_i, r_iI, b1, b2, Wr, br, mapping);
    cmb_final<<<NB, FEAT>>>(out);
}